// round 1
// baseline (speedup 1.0000x reference)
#include <cuda_runtime.h>

// Problem constants (from reference setup_inputs)
#define B 8
#define H 100
#define W 100
#define C 512
#define R 300
#define POOL 7

// One block per output cell (b, r, py, px).
// 128 threads * float4 = 512 channels.
__global__ __launch_bounds__(128) void roi_align_kernel(
    const float* __restrict__ x,     // (B, H, W, C)
    const int*   __restrict__ rois,  // (R, 4): x1, y1, w, h
    float*       __restrict__ out)   // (B, R, 7, 7, C)
{
    int idx  = blockIdx.x;                 // ((b*R + r)*49 + cell)
    int cell = idx % 49;
    int tmp  = idx / 49;
    int r    = tmp % R;
    int b    = tmp / R;
    int py   = cell / POOL;
    int px   = cell % POOL;

    // ROI (16B-aligned: 4 ints per roi)
    const int4 roi = __ldg(((const int4*)rois) + r);
    const int x1 = roi.x, y1 = roi.y, w = roi.z, h = roi.w;

    // --- y axis coords (replicates JAX fp32 math) ---
    float sh = (float)h;
    float vy = ((float)py + 0.5f) * (sh / (float)POOL) - 0.5f;
    vy = fminf(fmaxf(vy, 0.0f), sh - 1.0f);
    float fly = floorf(vy);
    int   ylo = (int)fly;
    float fy  = vy - fly;
    int   yhi = min(ylo + 1, h - 1);
    int yl = y1 + ylo;
    int yh = y1 + yhi;

    // --- x axis coords ---
    float sw = (float)w;
    float vx = ((float)px + 0.5f) * (sw / (float)POOL) - 0.5f;
    vx = fminf(fmaxf(vx, 0.0f), sw - 1.0f);
    float flx = floorf(vx);
    int   xlo = (int)flx;
    float fx  = vx - flx;
    int   xhi = min(xlo + 1, w - 1);
    int xl = x1 + xlo;
    int xh = x1 + xhi;

    // Base element offsets into x (channel-contiguous rows of 512 floats)
    long bHW = (long)b * H;
    const float* p_tl = x + (((bHW + yl) * W + xl) * (long)C);
    const float* p_tr = x + (((bHW + yl) * W + xh) * (long)C);
    const float* p_bl = x + (((bHW + yh) * W + xl) * (long)C);
    const float* p_br = x + (((bHW + yh) * W + xh) * (long)C);

    int c = threadIdx.x * 4;

    float4 tl = *(const float4*)(p_tl + c);
    float4 tr = *(const float4*)(p_tr + c);
    float4 bl = *(const float4*)(p_bl + c);
    float4 br = *(const float4*)(p_br + c);

    // top = tl + (tr - tl) * fx ; bot = bl + (br - bl) * fx ; out = top + (bot - top) * fy
    float4 o;
    {
        float top, bot;
        top = tl.x + (tr.x - tl.x) * fx;
        bot = bl.x + (br.x - bl.x) * fx;
        o.x = top + (bot - top) * fy;
        top = tl.y + (tr.y - tl.y) * fx;
        bot = bl.y + (br.y - bl.y) * fx;
        o.y = top + (bot - top) * fy;
        top = tl.z + (tr.z - tl.z) * fx;
        bot = bl.z + (br.z - bl.z) * fx;
        o.z = top + (bot - top) * fy;
        top = tl.w + (tr.w - tl.w) * fx;
        bot = bl.w + (br.w - bl.w) * fx;
        o.w = top + (bot - top) * fy;
    }

    // out index: (((b*R + r)*7 + py)*7 + px)*C + c  == idx * C + c
    float* po = out + (long)idx * C;
    *(float4*)(po + c) = o;
}

extern "C" void kernel_launch(void* const* d_in, const int* in_sizes, int n_in,
                              void* d_out, int out_size)
{
    const float* x    = (const float*)d_in[0];
    const int*   rois = (const int*)d_in[1];
    float*       out  = (float*)d_out;

    dim3 grid(B * R * POOL * POOL);   // 117,600 blocks
    roi_align_kernel<<<grid, 128>>>(x, rois, out);
}

// round 2
// speedup vs baseline: 1.0603x; 1.0603x over previous
#include <cuda_runtime.h>

// Problem constants (from reference setup_inputs)
#define B 8
#define H 100
#define W 100
#define C 512
#define R 300
#define POOL 7
#define NCELL (R * POOL * POOL)   // 14700

// Precomputed per-(roi, cell) data, batch-independent.
__device__ int4   g_offs[NCELL];   // element offsets of tl, tr, bl, br within one batch slice
__device__ float4 g_wts[NCELL];    // bilinear weights w_tl, w_tr, w_bl, w_br

__global__ void precompute_kernel(const int* __restrict__ rois)
{
    int i = blockIdx.x * blockDim.x + threadIdx.x;
    if (i >= NCELL) return;

    int r    = i / 49;
    int cell = i - r * 49;
    int py   = cell / POOL;
    int px   = cell - py * POOL;

    const int4 roi = __ldg(((const int4*)rois) + r);
    const int x1 = roi.x, y1 = roi.y, w = roi.z, h = roi.w;

    // y axis (replicates JAX fp32 math)
    float sh = (float)h;
    float vy = ((float)py + 0.5f) * (sh / (float)POOL) - 0.5f;
    vy = fminf(fmaxf(vy, 0.0f), sh - 1.0f);
    float fly = floorf(vy);
    int   ylo = (int)fly;
    float fy  = vy - fly;
    int   yhi = min(ylo + 1, h - 1);
    int yl = y1 + ylo;
    int yh = y1 + yhi;

    // x axis
    float sw = (float)w;
    float vx = ((float)px + 0.5f) * (sw / (float)POOL) - 0.5f;
    vx = fminf(fmaxf(vx, 0.0f), sw - 1.0f);
    float flx = floorf(vx);
    int   xlo = (int)flx;
    float fx  = vx - flx;
    int   xhi = min(xlo + 1, w - 1);
    int xl = x1 + xlo;
    int xh = x1 + xhi;

    int4 o;
    o.x = (yl * W + xl) * C;   // tl
    o.y = (yl * W + xh) * C;   // tr
    o.z = (yh * W + xl) * C;   // bl
    o.w = (yh * W + xh) * C;   // br
    g_offs[i] = o;

    float gx = 1.0f - fx;
    float gy = 1.0f - fy;
    float4 wt;
    wt.x = gx * gy;   // tl
    wt.y = fx * gy;   // tr
    wt.z = gx * fy;   // bl
    wt.w = fx * fy;   // br
    g_wts[i] = wt;
}

// grid: (R*49, B). One block per output cell; 128 threads * float4 = 512 channels.
__global__ __launch_bounds__(128) void roi_align_kernel(
    const float* __restrict__ x,    // (B, H, W, C)
    float*       __restrict__ out)  // (B, R, 7, 7, C)
{
    const int rc = blockIdx.x;      // r*49 + cell
    const int b  = blockIdx.y;

    const int4   o4 = g_offs[rc];
    const float4 wt = g_wts[rc];

    const float* base = x + (size_t)b * (H * W * C);
    const int c = threadIdx.x * 4;

    float4 tl = *(const float4*)(base + o4.x + c);
    float4 tr = *(const float4*)(base + o4.y + c);
    float4 bl = *(const float4*)(base + o4.z + c);
    float4 br = *(const float4*)(base + o4.w + c);

    float4 o;
    o.x = fmaf(br.x, wt.w, fmaf(bl.x, wt.z, fmaf(tr.x, wt.y, tl.x * wt.x)));
    o.y = fmaf(br.y, wt.w, fmaf(bl.y, wt.z, fmaf(tr.y, wt.y, tl.y * wt.x)));
    o.z = fmaf(br.z, wt.w, fmaf(bl.z, wt.z, fmaf(tr.z, wt.y, tl.z * wt.x)));
    o.w = fmaf(br.w, wt.w, fmaf(bl.w, wt.z, fmaf(tr.w, wt.y, tl.w * wt.x)));

    // out offset: (b*R*49 + rc)*C + c  — output is never re-read: streaming store
    float* po = out + ((size_t)b * NCELL + rc) * C + c;
    __stcs((float4*)po, o);
}

extern "C" void kernel_launch(void* const* d_in, const int* in_sizes, int n_in,
                              void* d_out, int out_size)
{
    const float* x    = (const float*)d_in[0];
    const int*   rois = (const int*)d_in[1];
    float*       out  = (float*)d_out;

    precompute_kernel<<<(NCELL + 127) / 128, 128>>>(rois);

    dim3 grid(NCELL, B);
    roi_align_kernel<<<grid, 128>>>(x, out);
}

// round 3
// speedup vs baseline: 1.1430x; 1.0780x over previous
#include <cuda_runtime.h>

// Problem constants (from reference setup_inputs)
#define B 8
#define H 100
#define W 100
#define C 512
#define R 300
#define POOL 7
#define NCELL (R * POOL * POOL)   // 14700

// Precomputed per-(roi, cell) data, batch-independent.
__device__ int4   g_offs[NCELL];   // element offsets of tl, tr, bl, br within one batch slice
__device__ float4 g_wts[NCELL];    // bilinear weights w_tl, w_tr, w_bl, w_br

__global__ void precompute_kernel(const int* __restrict__ rois)
{
    int i = blockIdx.x * blockDim.x + threadIdx.x;
    if (i >= NCELL) return;

    int r    = i / 49;
    int cell = i - r * 49;
    int py   = cell / POOL;
    int px   = cell - py * POOL;

    const int4 roi = __ldg(((const int4*)rois) + r);
    const int x1 = roi.x, y1 = roi.y, w = roi.z, h = roi.w;

    // y axis (replicates JAX fp32 math)
    float sh = (float)h;
    float vy = ((float)py + 0.5f) * (sh / (float)POOL) - 0.5f;
    vy = fminf(fmaxf(vy, 0.0f), sh - 1.0f);
    float fly = floorf(vy);
    int   ylo = (int)fly;
    float fy  = vy - fly;
    int   yhi = min(ylo + 1, h - 1);
    int yl = y1 + ylo;
    int yh = y1 + yhi;

    // x axis
    float sw = (float)w;
    float vx = ((float)px + 0.5f) * (sw / (float)POOL) - 0.5f;
    vx = fminf(fmaxf(vx, 0.0f), sw - 1.0f);
    float flx = floorf(vx);
    int   xlo = (int)flx;
    float fx  = vx - flx;
    int   xhi = min(xlo + 1, w - 1);
    int xl = x1 + xlo;
    int xh = x1 + xhi;

    int4 o;
    o.x = (yl * W + xl) * C;   // tl
    o.y = (yl * W + xh) * C;   // tr
    o.z = (yh * W + xl) * C;   // bl
    o.w = (yh * W + xh) * C;   // br
    g_offs[i] = o;

    float gx = 1.0f - fx;
    float gy = 1.0f - fy;
    float4 wt;
    wt.x = gx * gy;   // tl
    wt.y = fx * gy;   // tr
    wt.z = gx * fy;   // bl
    wt.w = fx * fy;   // br
    g_wts[i] = wt;
}

// grid: (R*7, B). One block per (roi, py) row; processes all 7 px cells with a
// 2-stage register pipeline (loads for px+1 issued before computing px).
// 128 threads * float4 = 512 channels.
__global__ __launch_bounds__(128) void roi_align_kernel(
    const float* __restrict__ x,    // (B, H, W, C)
    float*       __restrict__ out)  // (B, R, 7, 7, C)
{
    const int rp = blockIdx.x;      // r*7 + py
    const int b  = blockIdx.y;
    const int i0 = rp * POOL;       // first cell index of this row

    const float* base = x + (size_t)b * (H * W * C);
    const int c = threadIdx.x * 4;
    float* po = out + ((size_t)b * NCELL + i0) * C + c;

    // Prologue: load corners for px = 0
    int4 o4 = g_offs[i0];
    float4 tl = *(const float4*)(base + o4.x + c);
    float4 tr = *(const float4*)(base + o4.y + c);
    float4 bl = *(const float4*)(base + o4.z + c);
    float4 br = *(const float4*)(base + o4.w + c);

    #pragma unroll
    for (int px = 0; px < POOL; ++px) {
        const float4 wt = g_wts[i0 + px];

        // retire current stage into locals
        const float4 ctl = tl, ctr = tr, cbl = bl, cbr = br;

        // issue next stage's loads before consuming current
        if (px < POOL - 1) {
            const int4 n4 = g_offs[i0 + px + 1];
            tl = *(const float4*)(base + n4.x + c);
            tr = *(const float4*)(base + n4.y + c);
            bl = *(const float4*)(base + n4.z + c);
            br = *(const float4*)(base + n4.w + c);
        }

        float4 o;
        o.x = fmaf(cbr.x, wt.w, fmaf(cbl.x, wt.z, fmaf(ctr.x, wt.y, ctl.x * wt.x)));
        o.y = fmaf(cbr.y, wt.w, fmaf(cbl.y, wt.z, fmaf(ctr.y, wt.y, ctl.y * wt.x)));
        o.z = fmaf(cbr.z, wt.w, fmaf(cbl.z, wt.z, fmaf(ctr.z, wt.y, ctl.z * wt.x)));
        o.w = fmaf(cbr.w, wt.w, fmaf(cbl.w, wt.z, fmaf(ctr.w, wt.y, ctl.w * wt.x)));

        // output is never re-read: streaming store
        __stcs((float4*)(po + px * C), o);
    }
}

extern "C" void kernel_launch(void* const* d_in, const int* in_sizes, int n_in,
                              void* d_out, int out_size)
{
    const float* x    = (const float*)d_in[0];
    const int*   rois = (const int*)d_in[1];
    float*       out  = (float*)d_out;

    precompute_kernel<<<(NCELL + 127) / 128, 128>>>(rois);

    dim3 grid(R * POOL, B);   // 16,800 blocks
    roi_align_kernel<<<grid, 128>>>(x, out);
}